// round 13
// baseline (speedup 1.0000x reference)
#include <cuda_runtime.h>
#include <stdint.h>
#include <math.h>

#define NB 64
#define NT 512
#define NF 512
#define NDIN 1024
#define NH 1024
#define NZ 4096
#define NDOUT 128
#define SH (NB*NH)     // 65536 floats per h buffer
#define NBLK 128       // persistent blocks (1/SM, all co-resident)
#define KCH 32         // k per chunk in k_rnn
#define RNN_THREADS 512
// smem: hs 64KB + ws 64KB + zred 96KB (parity-doubled)
#define RNN_SMEM (65536 + 65536 + 98304)

typedef unsigned long long ull;

// Scratch (device globals; no dynamic allocation allowed)
__device__ float g_xin[(size_t)NT * NB * NDIN];   // tanh(x@Wi+bi), rows r = t*NB+b
__device__ float g_P0[(size_t)NT * NB * NZ];      // xin@W0 + b0
__device__ float g_h0T[2 * SH];                   // transposed h0: [par][j][64 rows]
__device__ float g_h1T[2 * SH];                   // transposed h1
// Region-1 weights (h0-driven), per-lane float2 {U0, W1}:
__device__ float g_WC[(size_t)NBLK * 1024 * 64];    // 32 MB
// Region-2 weights (h1-driven): U1
__device__ float g_WD[(size_t)NBLK * 1024 * 32];    // 16 MB

// dataflow sync state
__device__ volatile unsigned g_hf0[NBLK];   // block b: h0(g_hf0[b]) available
__device__ volatile unsigned g_hf1[NBLK];   // block b: h1(g_hf1[b]) available
__device__ volatile unsigned g_done[NBLK];  // block b: loads of phase (g_done[b]-1) complete
__device__ volatile unsigned g_allmin;      // all blocks' loads of phase (g_allmin-1) complete

// ---------------------------------------------------------------------------
// packed f32x2 helpers (sm_103a dual-fp32 pipe, PTX-only)
// ---------------------------------------------------------------------------
__device__ __forceinline__ ull ffma2_(ull a, ull b, ull c) {
    ull d;
    asm("fma.rn.f32x2 %0, %1, %2, %3;" : "=l"(d) : "l"(a), "l"(b), "l"(c));
    return d;
}
__device__ __forceinline__ ull addf2_(ull a, ull b) {
    ull d;
    asm("add.rn.f32x2 %0, %1, %2;" : "=l"(d) : "l"(a), "l"(b));
    return d;
}
__device__ __forceinline__ float2 unpack2_(ull v) {
    float2 r;
    asm("mov.b64 {%0, %1}, %2;" : "=f"(r.x), "=f"(r.y) : "l"(v));
    return r;
}
__device__ __forceinline__ ull dup2_(float f) {
    ull d;
    asm("mov.b64 %0, {%1, %1};" : "=l"(d) : "f"(f));
    return d;
}

// cp.async, L2-only (.cg) — bypasses L1 so cross-SM h updates are never stale
__device__ __forceinline__ void cp16_(uint32_t dst, const void* src) {
    asm volatile("cp.async.cg.shared.global [%0], [%1], 16;" :: "r"(dst), "l"(src));
}
#define CPCOMMIT() asm volatile("cp.async.commit_group;" ::: "memory")
#define CPWAIT1()  asm volatile("cp.async.wait_group 1;"  ::: "memory")

__device__ __forceinline__ float sigmoidf_(float v) {
    return 1.f / (1.f + __expf(-v));
}

// ---------------------------------------------------------------------------
__global__ void k_init() {
    int idx = blockIdx.x * blockDim.x + threadIdx.x;
    if (idx < 2 * SH) { g_h0T[idx] = 0.f; g_h1T[idx] = 0.f; }
    if (idx < NBLK) { g_hf0[idx] = 0; g_hf1[idx] = 0; g_done[idx] = 0; }
    if (idx == 0) g_allmin = 0;
}

// ---------------------------------------------------------------------------
// k_prep: pack recurrent weights into block-major lane streams.
// ---------------------------------------------------------------------------
__global__ void k_prep(const float* __restrict__ U0, const float* __restrict__ W1,
                       const float* __restrict__ U1) {
    int idx = blockIdx.x * blockDim.x + threadIdx.x;
    const int NWC = NBLK * 1024 * 64;      // 8M
    const int NWD = NBLK * 1024 * 32;      // 4M
    if (idx < NWC) {
        int lane2 = idx & 63, k = (idx >> 6) & 1023, b = idx >> 16;
        int lane = lane2 >> 1, which = lane2 & 1;
        int col = (lane >> 3) * NH + b * 8 + (lane & 7);
        g_WC[idx] = which ? W1[(size_t)k * NZ + col] : U0[(size_t)k * NZ + col];
    }
    if (idx < NWD) {
        int lane = idx & 31, k = (idx >> 5) & 1023, b = idx >> 15;
        int col = (lane >> 3) * NH + b * 8 + (lane & 7);
        g_WD[idx] = U1[(size_t)k * NZ + col];
    }
}

// ---------------------------------------------------------------------------
// k_xin: xin[r, n] = tanh( x[b,t,:] @ Wi[:,n] + bi[n] ),  r = t*NB + b
// ---------------------------------------------------------------------------
__global__ __launch_bounds__(256) void k_xin(const float* __restrict__ x,
                                             const float* __restrict__ Wi,
                                             const float* __restrict__ bi) {
    __shared__ float As[16][64];
    __shared__ float Bs[16][64];
    int tid = threadIdx.x;
    int tx = tid & 15, ty = tid >> 4;
    int n0 = blockIdx.x * 64;
    int row0 = blockIdx.y * 64;

    float acc[4][4] = {};

    int ar = tid & 63, akq = tid >> 6;
    int R = row0 + ar;
    int bb = R & 63, tt = R >> 6;               // r = t*NB + b
    const float* aptr = x + ((size_t)bb * NT + tt) * NF + akq * 4;
    int bkk = tid >> 4, bnq = tid & 15;
    const float* bptr = Wi + (size_t)bkk * NDIN + n0 + bnq * 4;

    float4 pa = *(const float4*)aptr;
    float4 pb = *(const float4*)bptr;

    const int NC = NF / 16;
    for (int c = 0; c < NC; c++) {
        As[akq * 4 + 0][ar] = pa.x; As[akq * 4 + 1][ar] = pa.y;
        As[akq * 4 + 2][ar] = pa.z; As[akq * 4 + 3][ar] = pa.w;
        *(float4*)&Bs[bkk][bnq * 4] = pb;
        __syncthreads();
        if (c + 1 < NC) {
            pa = *(const float4*)(aptr + (c + 1) * 16);
            pb = *(const float4*)(bptr + (size_t)(c + 1) * 16 * NDIN);
        }
#pragma unroll
        for (int kk = 0; kk < 16; kk++) {
            float4 a = *(const float4*)&As[kk][ty * 4];
            float4 b = *(const float4*)&Bs[kk][tx * 4];
            acc[0][0] += a.x * b.x; acc[0][1] += a.x * b.y; acc[0][2] += a.x * b.z; acc[0][3] += a.x * b.w;
            acc[1][0] += a.y * b.x; acc[1][1] += a.y * b.y; acc[1][2] += a.y * b.z; acc[1][3] += a.y * b.w;
            acc[2][0] += a.z * b.x; acc[2][1] += a.z * b.y; acc[2][2] += a.z * b.z; acc[2][3] += a.z * b.w;
            acc[3][0] += a.w * b.x; acc[3][1] += a.w * b.y; acc[3][2] += a.w * b.z; acc[3][3] += a.w * b.w;
        }
        __syncthreads();
    }
#pragma unroll
    for (int i = 0; i < 4; i++) {
        int r = row0 + ty * 4 + i;
#pragma unroll
        for (int jx = 0; jx < 4; jx++) {
            int n = n0 + tx * 4 + jx;
            g_xin[(size_t)r * NDIN + n] = tanhf(acc[i][jx] + bi[n]);
        }
    }
}

// ---------------------------------------------------------------------------
// k_p0 v3 (round-10 version): P0 = xin @ W0 + b0. FFMA2 with register-dup A
// and natural f32x2 column pairs from plain Bs.
// ---------------------------------------------------------------------------
__global__ __launch_bounds__(256) void k_p0(const float* __restrict__ W0,
                                            const float* __restrict__ b0) {
    __shared__ float As[16][128];
    __shared__ float Bs[16][64];
    int tid = threadIdx.x;
    int tx = tid & 15, ty = tid >> 4;
    int n0 = blockIdx.x * 64;
    int row0 = blockIdx.y * 128;

    ull acc[8][2] = {};              // [row][colpair]

    int ar = tid & 127, akq0 = tid >> 7;
    const float* aptr0 = g_xin + (size_t)(row0 + ar) * NDIN + akq0 * 4;
    const float* aptr1 = g_xin + (size_t)(row0 + ar) * NDIN + (akq0 + 2) * 4;
    int bkk = tid >> 4, bnq = tid & 15;
    const float* bptr = W0 + (size_t)bkk * NZ + n0 + bnq * 4;

    float4 pa0 = *(const float4*)aptr0;
    float4 pa1 = *(const float4*)aptr1;
    float4 pb  = *(const float4*)bptr;

    const int NC = NDIN / 16;
    for (int c = 0; c < NC; c++) {
        As[akq0 * 4 + 0][ar] = pa0.x; As[akq0 * 4 + 1][ar] = pa0.y;
        As[akq0 * 4 + 2][ar] = pa0.z; As[akq0 * 4 + 3][ar] = pa0.w;
        As[(akq0 + 2) * 4 + 0][ar] = pa1.x; As[(akq0 + 2) * 4 + 1][ar] = pa1.y;
        As[(akq0 + 2) * 4 + 2][ar] = pa1.z; As[(akq0 + 2) * 4 + 3][ar] = pa1.w;
        *(float4*)&Bs[bkk][bnq * 4] = pb;
        __syncthreads();
        if (c + 1 < NC) {
            pa0 = *(const float4*)(aptr0 + (c + 1) * 16);
            pa1 = *(const float4*)(aptr1 + (c + 1) * 16);
            pb  = *(const float4*)(bptr + (size_t)(c + 1) * 16 * NZ);
        }
#pragma unroll
        for (int kk = 0; kk < 16; kk++) {
            float4 a0 = *(const float4*)&As[kk][ty * 8];
            float4 a1 = *(const float4*)&As[kk][ty * 8 + 4];
            ulonglong2 b = *(const ulonglong2*)&Bs[kk][tx * 4];
            ull d;
            d = dup2_(a0.x); acc[0][0] = ffma2_(d, b.x, acc[0][0]); acc[0][1] = ffma2_(d, b.y, acc[0][1]);
            d = dup2_(a0.y); acc[1][0] = ffma2_(d, b.x, acc[1][0]); acc[1][1] = ffma2_(d, b.y, acc[1][1]);
            d = dup2_(a0.z); acc[2][0] = ffma2_(d, b.x, acc[2][0]); acc[2][1] = ffma2_(d, b.y, acc[2][1]);
            d = dup2_(a0.w); acc[3][0] = ffma2_(d, b.x, acc[3][0]); acc[3][1] = ffma2_(d, b.y, acc[3][1]);
            d = dup2_(a1.x); acc[4][0] = ffma2_(d, b.x, acc[4][0]); acc[4][1] = ffma2_(d, b.y, acc[4][1]);
            d = dup2_(a1.y); acc[5][0] = ffma2_(d, b.x, acc[5][0]); acc[5][1] = ffma2_(d, b.y, acc[5][1]);
            d = dup2_(a1.z); acc[6][0] = ffma2_(d, b.x, acc[6][0]); acc[6][1] = ffma2_(d, b.y, acc[6][1]);
            d = dup2_(a1.w); acc[7][0] = ffma2_(d, b.x, acc[7][0]); acc[7][1] = ffma2_(d, b.y, acc[7][1]);
        }
        __syncthreads();
    }
#pragma unroll
    for (int i = 0; i < 8; i++) {
        int r = row0 + ty * 8 + i;
        int n = n0 + tx * 4;
        float2 vA = unpack2_(acc[i][0]);
        float2 vB = unpack2_(acc[i][1]);
        g_P0[(size_t)r * NZ + n + 0] = vA.x + b0[n + 0];
        g_P0[(size_t)r * NZ + n + 1] = vA.y + b0[n + 1];
        g_P0[(size_t)r * NZ + n + 2] = vB.x + b0[n + 2];
        g_P0[(size_t)r * NZ + n + 3] = vB.y + b0[n + 3];
    }
}

// ---------------------------------------------------------------------------
// 4x4 transpose among lanes {u, u+8, u+16, u+24} (bits 3,4 of lane).
// ---------------------------------------------------------------------------
__device__ __forceinline__ void transpose4_(ull acc[4], int g) {
    ull x0 = (g & 1) ? acc[0] : acc[1];
    ull x1 = (g & 1) ? acc[2] : acc[3];
    x0 = __shfl_xor_sync(0xffffffffu, x0, 8);
    x1 = __shfl_xor_sync(0xffffffffu, x1, 8);
    if (g & 1) { acc[0] = x0; acc[2] = x1; } else { acc[1] = x0; acc[3] = x1; }
    x0 = (g & 2) ? acc[0] : acc[2];
    x1 = (g & 2) ? acc[1] : acc[3];
    x0 = __shfl_xor_sync(0xffffffffu, x0, 16);
    x1 = __shfl_xor_sync(0xffffffffu, x1, 16);
    if (g & 2) { acc[0] = x0; acc[1] = x1; } else { acc[2] = x0; acc[3] = x1; }
}

// ---------------------------------------------------------------------------
// k_rnn v6: merged-phase recurrence, NO grid barrier — dataflow flags.
// Phase p: z0(p) (h0(p+1), p<512) and z1(p-1) (h1(p), p>0), one 3072-K pass.
// 4-way split-K, named barrier per grp. Dual epilogue (grp0: layer0, grp1:
// layer1). Sync protocol:
//   - consumers poll per-chunk producer flags (4 blocks per 32-k chunk):
//       region1 chunk c needs g_hf0[32*grp+4c .. +3] >= p
//       region2 chunk c needs g_hf1[32*grp+4(c-8) .. +3] >= p-1
//   - producers publish flags after fenced h stores
//   - WAR backpressure: writers wait g_allmin >= p (all blocks' phase-(p-1)
//     loads complete); block0's grp3 aggregates g_done -> g_allmin (1-phase
//     slack keeps it off the critical path)
//   - zred parity-double-buffered (no cross-phase intra-block race)
// ---------------------------------------------------------------------------
__global__ __launch_bounds__(RNN_THREADS, 1) void k_rnn(const float* __restrict__ b1) {
    extern __shared__ __align__(16) unsigned char sraw[];
    // hs [4][2][32][64] 64KB | ws [4][2][2048f] 64KB | zred[2 parities] 96KB
    ull* zbase = (ull*)(sraw + 131072);

    int tid = threadIdx.x;
    int grp = tid >> 7, gtid = tid & 127;
    int wg = (gtid >> 5), lane = tid & 31;
    int u = lane & 7, g = lane >> 3;
    int bid = blockIdx.x, j = bid * 8 + u;
    int R = wg * 16 + g * 4;                     // epilogue base row

    uint32_t sbase = (uint32_t)__cvta_generic_to_shared(sraw);
    uint32_t hdst = sbase + grp * 16384;
    uint32_t wdst = sbase + 65536 + grp * 16384;
    const float* hs_rd = (const float*)sraw + grp * 4096;
    const float* ws_rd = (const float*)(sraw + 65536) + grp * 4096;

    const float* wcg = g_WC + (size_t)bid * 1024 * 64 + (size_t)grp * 256 * 64;
    const float* wdg = g_WD + (size_t)bid * 1024 * 32 + (size_t)grp * 256 * 32;

    float b1v[4];
#pragma unroll
    for (int m = 0; m < 4; m++) b1v[m] = b1[m * NH + j];
    float c0[4] = {0.f, 0.f, 0.f, 0.f};
    float c1[4] = {0.f, 0.f, 0.f, 0.f};

    for (int p = 0; p <= NT; p++) {
        int par = p & 1;
        const float* h0g = g_h0T + (size_t)par * SH + (size_t)grp * 256 * 64;
        const float* h1g = g_h1T + (size_t)(par ^ 1) * SH + (size_t)grp * 256 * 64;
        float* h0w = g_h0T + (size_t)(par ^ 1) * SH;   // h0(p+1)
        float* h1w = g_h1T + (size_t)par * SH;         // h1(p)
        ull* zredA = zbase + (size_t)par * 6144;
        ull* zredB = zredA + 3072;

        unsigned needA = (unsigned)p;                  // h0(p) flags
        unsigned needB = (p == 0) ? 0u : (unsigned)(p - 1);  // h1(p-1) flags

        // P0 prefetch for layer-0 epilogue (grp 0 only, p<512)
        float pz[4][4];
        if (grp == 0 && p < NT) {
            size_t pb = ((size_t)p * NB + R) * NZ + j;
#pragma unroll
            for (int r = 0; r < 4; r++)
#pragma unroll
                for (int m = 0; m < 4; m++)
                    pz[r][m] = g_P0[pb + (size_t)r * NZ + m * NH];
        }

        ull accA[8] = {0ull,0ull,0ull,0ull,0ull,0ull,0ull,0ull};
        ull accB[8] = {0ull,0ull,0ull,0ull,0ull,0ull,0ull,0ull};

        auto barg = [&] {
            asm volatile("bar.sync %0, %1;" :: "r"(grp + 1), "r"(128) : "memory");
        };
        auto load = [&](int buf, int c) {
            const char* hp;
            const char* wp;
            int nw;
            if (c < 8) {
                int pb = grp * 32 + c * 4;
                while (g_hf0[pb] < needA || g_hf0[pb + 1] < needA ||
                       g_hf0[pb + 2] < needA || g_hf0[pb + 3] < needA) { }
                hp = (const char*)(h0g + c * 2048);
                wp = (const char*)(wcg + (size_t)c * 2048);
                nw = 4;
            } else {
                int pb = grp * 32 + (c - 8) * 4;
                while (g_hf1[pb] < needB || g_hf1[pb + 1] < needB ||
                       g_hf1[pb + 2] < needB || g_hf1[pb + 3] < needB) { }
                hp = (const char*)(h1g + (c - 8) * 2048);
                wp = (const char*)(wdg + (size_t)(c - 8) * 1024);
                nw = 2;
            }
            hp += gtid * 16;
            uint32_t hd = hdst + buf * 8192 + gtid * 16;
            cp16_(hd, hp); cp16_(hd + 2048, hp + 2048);
            cp16_(hd + 4096, hp + 4096); cp16_(hd + 6144, hp + 6144);
            wp += gtid * 16;
            uint32_t wd = wdst + buf * 8192 + gtid * 16;
            cp16_(wd, wp); cp16_(wd + 2048, wp + 2048);
            if (nw == 4) { cp16_(wd + 4096, wp + 4096); cp16_(wd + 6144, wp + 6144); }
        };

        load(0, 0); CPCOMMIT();
        load(1, 1); CPCOMMIT();
        CPWAIT1(); barg();

        for (int c = 0; c < 16; c++) {
            int buf = c & 1;
            const float* hC = hs_rd + buf * 2048 + wg * 16;
            if (c < 8) {
                const float2* wC = (const float2*)(ws_rd + buf * 2048);
#pragma unroll 8
                for (int kk = 0; kk < KCH; kk++) {
                    ulonglong2 hA = *(const ulonglong2*)(hC + kk * 64);
                    ulonglong2 hB = *(const ulonglong2*)(hC + kk * 64 + 4);
                    ulonglong2 hCc = *(const ulonglong2*)(hC + kk * 64 + 8);
                    ulonglong2 hD = *(const ulonglong2*)(hC + kk * 64 + 12);
                    float2 wv = wC[kk * 32 + lane];
                    ull d0 = dup2_(wv.x);
                    ull d1 = dup2_(wv.y);
                    accA[0] = ffma2_(hA.x, d0, accA[0]);
                    accA[1] = ffma2_(hA.y, d0, accA[1]);
                    accA[2] = ffma2_(hB.x, d0, accA[2]);
                    accA[3] = ffma2_(hB.y, d0, accA[3]);
                    accA[4] = ffma2_(hCc.x, d0, accA[4]);
                    accA[5] = ffma2_(hCc.y, d0, accA[5]);
                    accA[6] = ffma2_(hD.x, d0, accA[6]);
                    accA[7] = ffma2_(hD.y, d0, accA[7]);
                    accB[0] = ffma2_(hA.x, d1, accB[0]);
                    accB[1] = ffma2_(hA.y, d1, accB[1]);
                    accB[2] = ffma2_(hB.x, d1, accB[2]);
                    accB[3] = ffma2_(hB.y, d1, accB[3]);
                    accB[4] = ffma2_(hCc.x, d1, accB[4]);
                    accB[5] = ffma2_(hCc.y, d1, accB[5]);
                    accB[6] = ffma2_(hD.x, d1, accB[6]);
                    accB[7] = ffma2_(hD.y, d1, accB[7]);
                }
            } else {
                const float* wC = ws_rd + buf * 2048;
#pragma unroll 8
                for (int kk = 0; kk < KCH; kk++) {
                    ulonglong2 hA = *(const ulonglong2*)(hC + kk * 64);
                    ulonglong2 hB = *(const ulonglong2*)(hC + kk * 64 + 4);
                    ulonglong2 hCc = *(const ulonglong2*)(hC + kk * 64 + 8);
                    ulonglong2 hD = *(const ulonglong2*)(hC + kk * 64 + 12);
                    ull d1 = dup2_(wC[kk * 32 + lane]);
                    accB[0] = ffma2_(hA.x, d1, accB[0]);
                    accB[1] = ffma2_(hA.y, d1, accB[1]);
                    accB[2] = ffma2_(hB.x, d1, accB[2]);
                    accB[3] = ffma2_(hB.y, d1, accB[3]);
                    accB[4] = ffma2_(hCc.x, d1, accB[4]);
                    accB[5] = ffma2_(hCc.y, d1, accB[5]);
                    accB[6] = ffma2_(hD.x, d1, accB[6]);
                    accB[7] = ffma2_(hD.y, d1, accB[7]);
                }
            }
            barg();
            if (c + 2 < 16) load(buf, c + 2);
            CPCOMMIT(); CPWAIT1(); barg();
        }

        // ---- write partials (A: grps 1-3; B: grps 0,2,3) ----
        if (grp != 0) {
            int base = ((grp - 1) * 4 + wg) * 8;
#pragma unroll
            for (int s = 0; s < 8; s++) zredA[(base + s) * 32 + lane] = accA[s];
        }
        if (grp != 1) {
            int qb = (grp == 0) ? 0 : grp - 1;
            int base = (qb * 4 + wg) * 8;
#pragma unroll
            for (int s = 0; s < 8; s++) zredB[(base + s) * 32 + lane] = accB[s];
        }
        __syncthreads();   // all loads of phase p complete; zred published

        if (tid == 256) g_done[bid] = (unsigned)(p + 1);

        if (bid == 0 && grp == 3) {
            // aggregate: all blocks done with phase-p loads -> release writers of p+1
            while (g_done[gtid] < (unsigned)(p + 1)) { }
            asm volatile("bar.sync 4, 128;" ::: "memory");
            if (gtid == 0) { __threadfence(); g_allmin = (unsigned)(p + 1); }
        }

        if (grp == 0 && p < NT) {
            // ---- layer-0 epilogue: h0(p+1) ----
#pragma unroll
            for (int q = 0; q < 3; q++) {
                int base = (q * 4 + wg) * 8;
#pragma unroll
                for (int s = 0; s < 8; s++)
                    accA[s] = addf2_(accA[s], zredA[(base + s) * 32 + lane]);
            }
            ull aE[4] = {accA[0], accA[2], accA[4], accA[6]};
            ull aO[4] = {accA[1], accA[3], accA[5], accA[7]};
            transpose4_(aE, g);
            transpose4_(aO, g);
            float zg[4][4];
#pragma unroll
            for (int m = 0; m < 4; m++) {
                float2 e = unpack2_(aE[m]), o = unpack2_(aO[m]);
                zg[m][0] = e.x; zg[m][1] = e.y; zg[m][2] = o.x; zg[m][3] = o.y;
            }
            float hv[4];
#pragma unroll
            for (int r = 0; r < 4; r++) {
                float ig = sigmoidf_(zg[0][r] + pz[r][0]);
                float fg = sigmoidf_(zg[1][r] + pz[r][1]);
                float gg = tanhf(zg[2][r] + pz[r][2]);
                float og = sigmoidf_(zg[3][r] + pz[r][3]);
                c0[r] = fg * c0[r] + ig * gg;
                hv[r] = og * tanhf(c0[r]);
            }
            if (p > 0) { while (g_allmin < (unsigned)p) { } }   // WAR: h0(p-1) readers done
            *(float4*)&h0w[j * 64 + R] = make_float4(hv[0], hv[1], hv[2], hv[3]);
            asm volatile("bar.sync 1, 128;" ::: "memory");
            if (gtid == 0) { __threadfence(); g_hf0[bid] = (unsigned)(p + 1); }
        } else if (grp == 1 && p > 0) {
            // ---- layer-1 epilogue: h1(p) ----
#pragma unroll
            for (int q = 0; q < 3; q++) {
                int base = (q * 4 + wg) * 8;
#pragma unroll
                for (int s = 0; s < 8; s++)
                    accB[s] = addf2_(accB[s], zredB[(base + s) * 32 + lane]);
            }
            ull aE[4] = {accB[0], accB[2], accB[4], accB[6]};
            ull aO[4] = {accB[1], accB[3], accB[5], accB[7]};
            transpose4_(aE, g);
            transpose4_(aO, g);
            float zg[4][4];
#pragma unroll
            for (int m = 0; m < 4; m++) {
                float2 e = unpack2_(aE[m]), o = unpack2_(aO[m]);
                zg[m][0] = e.x; zg[m][1] = e.y; zg[m][2] = o.x; zg[m][3] = o.y;
            }
            float hv[4];
#pragma unroll
            for (int r = 0; r < 4; r++) {
                float ig = sigmoidf_(zg[0][r] + b1v[0]);
                float fg = sigmoidf_(zg[1][r] + b1v[1]);
                float gg = tanhf(zg[2][r] + b1v[2]);
                float og = sigmoidf_(zg[3][r] + b1v[3]);
                c1[r] = fg * c1[r] + ig * gg;
                hv[r] = og * tanhf(c1[r]);
            }
            while (g_allmin < (unsigned)p) { }                  // WAR: h1(p-2) readers done
            *(float4*)&h1w[j * 64 + R] = make_float4(hv[0], hv[1], hv[2], hv[3]);
            asm volatile("bar.sync 2, 128;" ::: "memory");
            if (gtid == 0) { __threadfence(); g_hf1[bid] = (unsigned)p; }
        }
        // no grid sync — next phase gated by per-chunk flags
    }
}

// ---------------------------------------------------------------------------
// k_out: out = tanh( h1_final @ Wo + bo ),  h1 stored transposed hT[k][b]
// ---------------------------------------------------------------------------
__global__ void k_out(const float* __restrict__ Wo, const float* __restrict__ bo,
                      float* __restrict__ out) {
    int idx = blockIdx.x * blockDim.x + threadIdx.x;
    if (idx >= NB * NDOUT) return;
    int n = idx & 127, b = idx >> 7;
    const float* hT = g_h1T;   // h1(512) at parity 0
    float s0 = 0.f, s1 = 0.f, s2 = 0.f, s3 = 0.f;
#pragma unroll 4
    for (int k = 0; k < NH; k += 4) {
        s0 += hT[(k + 0) * 64 + b] * Wo[(size_t)(k + 0) * NDOUT + n];
        s1 += hT[(k + 1) * 64 + b] * Wo[(size_t)(k + 1) * NDOUT + n];
        s2 += hT[(k + 2) * 64 + b] * Wo[(size_t)(k + 2) * NDOUT + n];
        s3 += hT[(k + 3) * 64 + b] * Wo[(size_t)(k + 3) * NDOUT + n];
    }
    out[idx] = tanhf((s0 + s1) + (s2 + s3) + bo[n]);
}

// ---------------------------------------------------------------------------
extern "C" void kernel_launch(void* const* d_in, const int* in_sizes, int n_in,
                              void* d_out, int out_size) {
    const float* x  = (const float*)d_in[0];
    const float* Wi = (const float*)d_in[1];
    const float* bi = (const float*)d_in[2];
    const float* W0 = (const float*)d_in[3];
    const float* U0 = (const float*)d_in[4];
    const float* b0 = (const float*)d_in[5];
    const float* W1 = (const float*)d_in[6];
    const float* U1 = (const float*)d_in[7];
    const float* b1 = (const float*)d_in[8];
    const float* Wo = (const float*)d_in[9];
    const float* bo = (const float*)d_in[10];
    float* out = (float*)d_out;
    (void)in_sizes; (void)n_in; (void)out_size;

    cudaFuncSetAttribute(k_rnn, cudaFuncAttributeMaxDynamicSharedMemorySize, RNN_SMEM);

    k_init<<<512, 256>>>();
    k_prep<<<32768, 256>>>(U0, W1, U1);
    k_xin<<<dim3(16, 512), 256>>>(x, Wi, bi);
    k_p0<<<dim3(64, 256), 256>>>(W0, b0);
    k_rnn<<<NBLK, RNN_THREADS, RNN_SMEM>>>(b1);
    k_out<<<32, 256>>>(Wo, bo, out);
}

// round 14
// speedup vs baseline: 1.1912x; 1.1912x over previous
#include <cuda_runtime.h>
#include <stdint.h>
#include <math.h>

#define NB 64
#define NT 512
#define NF 512
#define NDIN 1024
#define NH 1024
#define NZ 4096
#define NDOUT 128
#define SH (NB*NH)     // 65536 floats per h buffer
#define NBLK 128       // persistent blocks (1/SM, all co-resident)
#define KCH 32         // k per chunk in k_rnn
#define RNN_THREADS 512
// smem: hs 64KB + ws 64KB + zred 48KB
#define RNN_SMEM (65536 + 65536 + 49152)

typedef unsigned long long ull;

// Scratch (device globals; no dynamic allocation allowed)
__device__ float g_xin[(size_t)NT * NB * NDIN];   // tanh(x@Wi+bi), rows r = t*NB+b
__device__ float g_P0[(size_t)NT * NB * NZ];      // xin@W0 + b0
__device__ float g_h0T[2 * SH];                   // transposed h0: [par][j][64 rows]
__device__ float g_h1T[2 * SH];                   // transposed h1
// Region-1 weights (h0-driven), per-lane float2 {U0, W1}:
__device__ float g_WC[(size_t)NBLK * 1024 * 64];    // 32 MB
// Region-2 weights (h1-driven): U1
__device__ float g_WD[(size_t)NBLK * 1024 * 32];    // 16 MB

// grid barrier state: per-block arrival flags + release generation
__device__ volatile unsigned g_flags[NBLK];
__device__ volatile unsigned g_relgen;

// ---------------------------------------------------------------------------
// packed f32x2 helpers (sm_103a dual-fp32 pipe, PTX-only)
// ---------------------------------------------------------------------------
__device__ __forceinline__ ull ffma2_(ull a, ull b, ull c) {
    ull d;
    asm("fma.rn.f32x2 %0, %1, %2, %3;" : "=l"(d) : "l"(a), "l"(b), "l"(c));
    return d;
}
__device__ __forceinline__ ull addf2_(ull a, ull b) {
    ull d;
    asm("add.rn.f32x2 %0, %1, %2;" : "=l"(d) : "l"(a), "l"(b));
    return d;
}
__device__ __forceinline__ float2 unpack2_(ull v) {
    float2 r;
    asm("mov.b64 {%0, %1}, %2;" : "=f"(r.x), "=f"(r.y) : "l"(v));
    return r;
}
__device__ __forceinline__ ull dup2_(float f) {
    ull d;
    asm("mov.b64 %0, {%1, %1};" : "=l"(d) : "f"(f));
    return d;
}

// cp.async, L2-only (.cg) — bypasses L1 so cross-SM h updates are never stale
__device__ __forceinline__ void cp16_(uint32_t dst, const void* src) {
    asm volatile("cp.async.cg.shared.global [%0], [%1], 16;" :: "r"(dst), "l"(src));
}
#define CPCOMMIT() asm volatile("cp.async.commit_group;" ::: "memory")
#define CPWAIT1()  asm volatile("cp.async.wait_group 1;"  ::: "memory")

__device__ __forceinline__ float sigmoidf_(float v) {
    return 1.f / (1.f + __expf(-v));
}

// ---------------------------------------------------------------------------
__global__ void k_init() {
    int idx = blockIdx.x * blockDim.x + threadIdx.x;
    if (idx < 2 * SH) { g_h0T[idx] = 0.f; g_h1T[idx] = 0.f; }
    if (idx < NBLK) g_flags[idx] = 0;
    if (idx == 0) g_relgen = 0;
}

// ---------------------------------------------------------------------------
// k_prep: pack recurrent weights into block-major lane streams.
// ---------------------------------------------------------------------------
__global__ void k_prep(const float* __restrict__ U0, const float* __restrict__ W1,
                       const float* __restrict__ U1) {
    int idx = blockIdx.x * blockDim.x + threadIdx.x;
    const int NWC = NBLK * 1024 * 64;      // 8M
    const int NWD = NBLK * 1024 * 32;      // 4M
    if (idx < NWC) {
        int lane2 = idx & 63, k = (idx >> 6) & 1023, b = idx >> 16;
        int lane = lane2 >> 1, which = lane2 & 1;
        int col = (lane >> 3) * NH + b * 8 + (lane & 7);
        g_WC[idx] = which ? W1[(size_t)k * NZ + col] : U0[(size_t)k * NZ + col];
    }
    if (idx < NWD) {
        int lane = idx & 31, k = (idx >> 5) & 1023, b = idx >> 15;
        int col = (lane >> 3) * NH + b * 8 + (lane & 7);
        g_WD[idx] = U1[(size_t)k * NZ + col];
    }
}

// ---------------------------------------------------------------------------
// k_xin: xin[r, n] = tanh( x[b,t,:] @ Wi[:,n] + bi[n] ),  r = t*NB + b
// ---------------------------------------------------------------------------
__global__ __launch_bounds__(256) void k_xin(const float* __restrict__ x,
                                             const float* __restrict__ Wi,
                                             const float* __restrict__ bi) {
    __shared__ float As[16][64];
    __shared__ float Bs[16][64];
    int tid = threadIdx.x;
    int tx = tid & 15, ty = tid >> 4;
    int n0 = blockIdx.x * 64;
    int row0 = blockIdx.y * 64;

    float acc[4][4] = {};

    int ar = tid & 63, akq = tid >> 6;
    int R = row0 + ar;
    int bb = R & 63, tt = R >> 6;               // r = t*NB + b
    const float* aptr = x + ((size_t)bb * NT + tt) * NF + akq * 4;
    int bkk = tid >> 4, bnq = tid & 15;
    const float* bptr = Wi + (size_t)bkk * NDIN + n0 + bnq * 4;

    float4 pa = *(const float4*)aptr;
    float4 pb = *(const float4*)bptr;

    const int NC = NF / 16;
    for (int c = 0; c < NC; c++) {
        As[akq * 4 + 0][ar] = pa.x; As[akq * 4 + 1][ar] = pa.y;
        As[akq * 4 + 2][ar] = pa.z; As[akq * 4 + 3][ar] = pa.w;
        *(float4*)&Bs[bkk][bnq * 4] = pb;
        __syncthreads();
        if (c + 1 < NC) {
            pa = *(const float4*)(aptr + (c + 1) * 16);
            pb = *(const float4*)(bptr + (size_t)(c + 1) * 16 * NDIN);
        }
#pragma unroll
        for (int kk = 0; kk < 16; kk++) {
            float4 a = *(const float4*)&As[kk][ty * 4];
            float4 b = *(const float4*)&Bs[kk][tx * 4];
            acc[0][0] += a.x * b.x; acc[0][1] += a.x * b.y; acc[0][2] += a.x * b.z; acc[0][3] += a.x * b.w;
            acc[1][0] += a.y * b.x; acc[1][1] += a.y * b.y; acc[1][2] += a.y * b.z; acc[1][3] += a.y * b.w;
            acc[2][0] += a.z * b.x; acc[2][1] += a.z * b.y; acc[2][2] += a.z * b.z; acc[2][3] += a.z * b.w;
            acc[3][0] += a.w * b.x; acc[3][1] += a.w * b.y; acc[3][2] += a.w * b.z; acc[3][3] += a.w * b.w;
        }
        __syncthreads();
    }
#pragma unroll
    for (int i = 0; i < 4; i++) {
        int r = row0 + ty * 4 + i;
#pragma unroll
        for (int jx = 0; jx < 4; jx++) {
            int n = n0 + tx * 4 + jx;
            g_xin[(size_t)r * NDIN + n] = tanhf(acc[i][jx] + bi[n]);
        }
    }
}

// ---------------------------------------------------------------------------
// k_p0 v5: P0 = xin @ W0 + b0. Tile 128x128, 256 threads, 8x8 per thread.
// Per kk: 4x LDS.128 feed 32 FFMA2 — crossbar and fma pipe balanced.
// ---------------------------------------------------------------------------
__global__ __launch_bounds__(256) void k_p0(const float* __restrict__ W0,
                                            const float* __restrict__ b0) {
    __shared__ float As[16][128];
    __shared__ float Bs[16][128];
    int tid = threadIdx.x;
    int tx = tid & 15, ty = tid >> 4;
    int n0 = blockIdx.x * 128;
    int row0 = blockIdx.y * 128;

    ull acc[8][4] = {};              // [row][colpair]

    // A loader: row ar, k-quads akq*4..+3 and akq*4+8..+11
    int ar = tid & 127, akq = tid >> 7;          // akq in {0,1}
    const float* aptr0 = g_xin + (size_t)(row0 + ar) * NDIN + akq * 4;
    const float* aptr1 = aptr0 + 8;
    // B loader: k row bkk, col octet bnq*8 (two float4s)
    int bkk = tid >> 4, bnq = tid & 15;
    const float* bptr0 = W0 + (size_t)bkk * NZ + n0 + bnq * 8;
    const float* bptr1 = bptr0 + 4;

    float4 pa0 = *(const float4*)aptr0;
    float4 pa1 = *(const float4*)aptr1;
    float4 pb0 = *(const float4*)bptr0;
    float4 pb1 = *(const float4*)bptr1;

    const int NC = NDIN / 16;
    for (int c = 0; c < NC; c++) {
        As[akq * 4 + 0][ar] = pa0.x; As[akq * 4 + 1][ar] = pa0.y;
        As[akq * 4 + 2][ar] = pa0.z; As[akq * 4 + 3][ar] = pa0.w;
        As[akq * 4 + 8][ar] = pa1.x; As[akq * 4 + 9][ar] = pa1.y;
        As[akq * 4 + 10][ar] = pa1.z; As[akq * 4 + 11][ar] = pa1.w;
        *(float4*)&Bs[bkk][bnq * 8]     = pb0;
        *(float4*)&Bs[bkk][bnq * 8 + 4] = pb1;
        __syncthreads();
        if (c + 1 < NC) {
            pa0 = *(const float4*)(aptr0 + (c + 1) * 16);
            pa1 = *(const float4*)(aptr1 + (c + 1) * 16);
            pb0 = *(const float4*)(bptr0 + (size_t)(c + 1) * 16 * NZ);
            pb1 = *(const float4*)(bptr1 + (size_t)(c + 1) * 16 * NZ);
        }
#pragma unroll
        for (int kk = 0; kk < 16; kk++) {
            float4 a0 = *(const float4*)&As[kk][ty * 8];
            float4 a1 = *(const float4*)&As[kk][ty * 8 + 4];
            ulonglong2 bA = *(const ulonglong2*)&Bs[kk][tx * 8];      // colpairs 0,1
            ulonglong2 bB = *(const ulonglong2*)&Bs[kk][tx * 8 + 4];  // colpairs 2,3
            ull d;
            d = dup2_(a0.x);
            acc[0][0] = ffma2_(d, bA.x, acc[0][0]); acc[0][1] = ffma2_(d, bA.y, acc[0][1]);
            acc[0][2] = ffma2_(d, bB.x, acc[0][2]); acc[0][3] = ffma2_(d, bB.y, acc[0][3]);
            d = dup2_(a0.y);
            acc[1][0] = ffma2_(d, bA.x, acc[1][0]); acc[1][1] = ffma2_(d, bA.y, acc[1][1]);
            acc[1][2] = ffma2_(d, bB.x, acc[1][2]); acc[1][3] = ffma2_(d, bB.y, acc[1][3]);
            d = dup2_(a0.z);
            acc[2][0] = ffma2_(d, bA.x, acc[2][0]); acc[2][1] = ffma2_(d, bA.y, acc[2][1]);
            acc[2][2] = ffma2_(d, bB.x, acc[2][2]); acc[2][3] = ffma2_(d, bB.y, acc[2][3]);
            d = dup2_(a0.w);
            acc[3][0] = ffma2_(d, bA.x, acc[3][0]); acc[3][1] = ffma2_(d, bA.y, acc[3][1]);
            acc[3][2] = ffma2_(d, bB.x, acc[3][2]); acc[3][3] = ffma2_(d, bB.y, acc[3][3]);
            d = dup2_(a1.x);
            acc[4][0] = ffma2_(d, bA.x, acc[4][0]); acc[4][1] = ffma2_(d, bA.y, acc[4][1]);
            acc[4][2] = ffma2_(d, bB.x, acc[4][2]); acc[4][3] = ffma2_(d, bB.y, acc[4][3]);
            d = dup2_(a1.y);
            acc[5][0] = ffma2_(d, bA.x, acc[5][0]); acc[5][1] = ffma2_(d, bA.y, acc[5][1]);
            acc[5][2] = ffma2_(d, bB.x, acc[5][2]); acc[5][3] = ffma2_(d, bB.y, acc[5][3]);
            d = dup2_(a1.z);
            acc[6][0] = ffma2_(d, bA.x, acc[6][0]); acc[6][1] = ffma2_(d, bA.y, acc[6][1]);
            acc[6][2] = ffma2_(d, bB.x, acc[6][2]); acc[6][3] = ffma2_(d, bB.y, acc[6][3]);
            d = dup2_(a1.w);
            acc[7][0] = ffma2_(d, bA.x, acc[7][0]); acc[7][1] = ffma2_(d, bA.y, acc[7][1]);
            acc[7][2] = ffma2_(d, bB.x, acc[7][2]); acc[7][3] = ffma2_(d, bB.y, acc[7][3]);
        }
        __syncthreads();
    }
    int n = n0 + tx * 8;
    float4 bv0 = *(const float4*)&b0[n];
    float4 bv1 = *(const float4*)&b0[n + 4];
#pragma unroll
    for (int i = 0; i < 8; i++) {
        int r = row0 + ty * 8 + i;
        float2 v0 = unpack2_(acc[i][0]);
        float2 v1 = unpack2_(acc[i][1]);
        float2 v2 = unpack2_(acc[i][2]);
        float2 v3 = unpack2_(acc[i][3]);
        float4 o0 = make_float4(v0.x + bv0.x, v0.y + bv0.y, v1.x + bv0.z, v1.y + bv0.w);
        float4 o1 = make_float4(v2.x + bv1.x, v2.y + bv1.y, v3.x + bv1.z, v3.y + bv1.w);
        *(float4*)&g_P0[(size_t)r * NZ + n]     = o0;
        *(float4*)&g_P0[(size_t)r * NZ + n + 4] = o1;
    }
}

// ---------------------------------------------------------------------------
// flag-array grid barrier (round-12 version)
// ---------------------------------------------------------------------------
__device__ __forceinline__ void grid_sync_(int bid, unsigned ph) {
    __syncthreads();
    if (threadIdx.x == 0) {
        __threadfence();
        g_flags[bid] = ph;
    }
    if (bid == 0) {
        if (threadIdx.x < NBLK) {
            while (g_flags[threadIdx.x] < ph) { }
        }
        __syncthreads();
        if (threadIdx.x == 0) g_relgen = ph;
    }
    if (threadIdx.x == 0) {
        while (g_relgen < ph) { }
        __threadfence();
    }
    __syncthreads();
}

// ---------------------------------------------------------------------------
// 4x4 transpose among lanes {u, u+8, u+16, u+24} (bits 3,4 of lane).
// ---------------------------------------------------------------------------
__device__ __forceinline__ void transpose4_(ull acc[4], int g) {
    ull x0 = (g & 1) ? acc[0] : acc[1];
    ull x1 = (g & 1) ? acc[2] : acc[3];
    x0 = __shfl_xor_sync(0xffffffffu, x0, 8);
    x1 = __shfl_xor_sync(0xffffffffu, x1, 8);
    if (g & 1) { acc[0] = x0; acc[2] = x1; } else { acc[1] = x0; acc[3] = x1; }
    x0 = (g & 2) ? acc[0] : acc[2];
    x1 = (g & 2) ? acc[1] : acc[3];
    x0 = __shfl_xor_sync(0xffffffffu, x0, 16);
    x1 = __shfl_xor_sync(0xffffffffu, x1, 16);
    if (g & 2) { acc[0] = x0; acc[1] = x1; } else { acc[2] = x0; acc[3] = x1; }
}

// ---------------------------------------------------------------------------
// k_rnn v5 (round-12 version): merged-phase recurrence + dual epilogue.
// Phase p: z0(p) (h0(p+1), p<512) and z1(p-1) (h1(p), p>0) in one 3072-K
// pass, one grid sync. 4-way split-K, named barrier per grp.
// Tail: grp 0 reduces+finishes layer 0, grp 1 layer 1, concurrently.
// ---------------------------------------------------------------------------
__global__ __launch_bounds__(RNN_THREADS, 1) void k_rnn(const float* __restrict__ b1) {
    extern __shared__ __align__(16) unsigned char sraw[];
    // hs [4][2][32][64] 64KB | ws [4][2][2048f] 64KB | zredA 24KB | zredB 24KB
    ull* zredA = (ull*)(sraw + 131072);
    ull* zredB = zredA + 3072;

    int tid = threadIdx.x;
    int grp = tid >> 7, gtid = tid & 127;
    int wg = (gtid >> 5), lane = tid & 31;
    int u = lane & 7, g = lane >> 3;
    int bid = blockIdx.x, j = bid * 8 + u;
    int R = wg * 16 + g * 4;                     // epilogue base row

    uint32_t sbase = (uint32_t)__cvta_generic_to_shared(sraw);
    uint32_t hdst = sbase + grp * 16384;
    uint32_t wdst = sbase + 65536 + grp * 16384;
    const float* hs_rd = (const float*)sraw + grp * 4096;
    const float* ws_rd = (const float*)(sraw + 65536) + grp * 4096;

    const float* wcg = g_WC + (size_t)bid * 1024 * 64 + (size_t)grp * 256 * 64;
    const float* wdg = g_WD + (size_t)bid * 1024 * 32 + (size_t)grp * 256 * 32;

    float b1v[4];
#pragma unroll
    for (int m = 0; m < 4; m++) b1v[m] = b1[m * NH + j];
    float c0[4] = {0.f, 0.f, 0.f, 0.f};
    float c1[4] = {0.f, 0.f, 0.f, 0.f};

    for (int p = 0; p <= NT; p++) {
        int par = p & 1;
        const float* h0g = g_h0T + (size_t)par * SH + (size_t)grp * 256 * 64;
        const float* h1g = g_h1T + (size_t)(par ^ 1) * SH + (size_t)grp * 256 * 64;
        float* h0w = g_h0T + (size_t)(par ^ 1) * SH;   // h0(p+1)
        float* h1w = g_h1T + (size_t)par * SH;         // h1(p)

        // P0 prefetch for layer-0 epilogue (grp 0 only, p<512)
        float pz[4][4];
        if (grp == 0 && p < NT) {
            size_t pb = ((size_t)p * NB + R) * NZ + j;
#pragma unroll
            for (int r = 0; r < 4; r++)
#pragma unroll
                for (int m = 0; m < 4; m++)
                    pz[r][m] = g_P0[pb + (size_t)r * NZ + m * NH];
        }

        ull accA[8] = {0ull,0ull,0ull,0ull,0ull,0ull,0ull,0ull};
        ull accB[8] = {0ull,0ull,0ull,0ull,0ull,0ull,0ull,0ull};

        auto barg = [&] {
            asm volatile("bar.sync %0, %1;" :: "r"(grp + 1), "r"(128) : "memory");
        };
        auto load = [&](int buf, int c) {
            const char* hp;
            const char* wp;
            int nw;
            if (c < 8) {
                hp = (const char*)(h0g + c * 2048);
                wp = (const char*)(wcg + (size_t)c * 2048);
                nw = 4;
            } else {
                hp = (const char*)(h1g + (c - 8) * 2048);
                wp = (const char*)(wdg + (size_t)(c - 8) * 1024);
                nw = 2;
            }
            hp += gtid * 16;
            uint32_t hd = hdst + buf * 8192 + gtid * 16;
            cp16_(hd, hp); cp16_(hd + 2048, hp + 2048);
            cp16_(hd + 4096, hp + 4096); cp16_(hd + 6144, hp + 6144);
            wp += gtid * 16;
            uint32_t wd = wdst + buf * 8192 + gtid * 16;
            cp16_(wd, wp); cp16_(wd + 2048, wp + 2048);
            if (nw == 4) { cp16_(wd + 4096, wp + 4096); cp16_(wd + 6144, wp + 6144); }
        };

        load(0, 0); CPCOMMIT();
        load(1, 1); CPCOMMIT();
        CPWAIT1(); barg();

        for (int c = 0; c < 16; c++) {
            int buf = c & 1;
            const float* hC = hs_rd + buf * 2048 + wg * 16;
            if (c < 8) {
                const float2* wC = (const float2*)(ws_rd + buf * 2048);
#pragma unroll 8
                for (int kk = 0; kk < KCH; kk++) {
                    ulonglong2 hA = *(const ulonglong2*)(hC + kk * 64);
                    ulonglong2 hB = *(const ulonglong2*)(hC + kk * 64 + 4);
                    ulonglong2 hCc = *(const ulonglong2*)(hC + kk * 64 + 8);
                    ulonglong2 hD = *(const ulonglong2*)(hC + kk * 64 + 12);
                    float2 wv = wC[kk * 32 + lane];
                    ull d0 = dup2_(wv.x);
                    ull d1 = dup2_(wv.y);
                    accA[0] = ffma2_(hA.x, d0, accA[0]);
                    accA[1] = ffma2_(hA.y, d0, accA[1]);
                    accA[2] = ffma2_(hB.x, d0, accA[2]);
                    accA[3] = ffma2_(hB.y, d0, accA[3]);
                    accA[4] = ffma2_(hCc.x, d0, accA[4]);
                    accA[5] = ffma2_(hCc.y, d0, accA[5]);
                    accA[6] = ffma2_(hD.x, d0, accA[6]);
                    accA[7] = ffma2_(hD.y, d0, accA[7]);
                    accB[0] = ffma2_(hA.x, d1, accB[0]);
                    accB[1] = ffma2_(hA.y, d1, accB[1]);
                    accB[2] = ffma2_(hB.x, d1, accB[2]);
                    accB[3] = ffma2_(hB.y, d1, accB[3]);
                    accB[4] = ffma2_(hCc.x, d1, accB[4]);
                    accB[5] = ffma2_(hCc.y, d1, accB[5]);
                    accB[6] = ffma2_(hD.x, d1, accB[6]);
                    accB[7] = ffma2_(hD.y, d1, accB[7]);
                }
            } else {
                const float* wC = ws_rd + buf * 2048;
#pragma unroll 8
                for (int kk = 0; kk < KCH; kk++) {
                    ulonglong2 hA = *(const ulonglong2*)(hC + kk * 64);
                    ulonglong2 hB = *(const ulonglong2*)(hC + kk * 64 + 4);
                    ulonglong2 hCc = *(const ulonglong2*)(hC + kk * 64 + 8);
                    ulonglong2 hD = *(const ulonglong2*)(hC + kk * 64 + 12);
                    ull d1 = dup2_(wC[kk * 32 + lane]);
                    accB[0] = ffma2_(hA.x, d1, accB[0]);
                    accB[1] = ffma2_(hA.y, d1, accB[1]);
                    accB[2] = ffma2_(hB.x, d1, accB[2]);
                    accB[3] = ffma2_(hB.y, d1, accB[3]);
                    accB[4] = ffma2_(hCc.x, d1, accB[4]);
                    accB[5] = ffma2_(hCc.y, d1, accB[5]);
                    accB[6] = ffma2_(hD.x, d1, accB[6]);
                    accB[7] = ffma2_(hD.y, d1, accB[7]);
                }
            }
            barg();
            if (c + 2 < 16) load(buf, c + 2);
            CPCOMMIT(); CPWAIT1(); barg();
        }

        // ---- write partials (A: grps 1-3; B: grps 0,2,3) ----
        if (grp != 0) {
            int base = ((grp - 1) * 4 + wg) * 8;
#pragma unroll
            for (int s = 0; s < 8; s++) zredA[(base + s) * 32 + lane] = accA[s];
        }
        if (grp != 1) {
            int qb = (grp == 0) ? 0 : grp - 1;
            int base = (qb * 4 + wg) * 8;
#pragma unroll
            for (int s = 0; s < 8; s++) zredB[(base + s) * 32 + lane] = accB[s];
        }
        __syncthreads();

        if (grp == 0 && p < NT) {
            // ---- layer-0 epilogue: h0(p+1) ----
#pragma unroll
            for (int q = 0; q < 3; q++) {
                int base = (q * 4 + wg) * 8;
#pragma unroll
                for (int s = 0; s < 8; s++)
                    accA[s] = addf2_(accA[s], zredA[(base + s) * 32 + lane]);
            }
            ull aE[4] = {accA[0], accA[2], accA[4], accA[6]};
            ull aO[4] = {accA[1], accA[3], accA[5], accA[7]};
            transpose4_(aE, g);
            transpose4_(aO, g);
            float zg[4][4];
#pragma unroll
            for (int m = 0; m < 4; m++) {
                float2 e = unpack2_(aE[m]), o = unpack2_(aO[m]);
                zg[m][0] = e.x; zg[m][1] = e.y; zg[m][2] = o.x; zg[m][3] = o.y;
            }
            float hv[4];
#pragma unroll
            for (int r = 0; r < 4; r++) {
                float ig = sigmoidf_(zg[0][r] + pz[r][0]);
                float fg = sigmoidf_(zg[1][r] + pz[r][1]);
                float gg = tanhf(zg[2][r] + pz[r][2]);
                float og = sigmoidf_(zg[3][r] + pz[r][3]);
                c0[r] = fg * c0[r] + ig * gg;
                hv[r] = og * tanhf(c0[r]);
            }
            *(float4*)&h0w[j * 64 + R] = make_float4(hv[0], hv[1], hv[2], hv[3]);
        } else if (grp == 1 && p > 0) {
            // ---- layer-1 epilogue: h1(p) ----
#pragma unroll
            for (int q = 0; q < 3; q++) {
                int base = (q * 4 + wg) * 8;
#pragma unroll
                for (int s = 0; s < 8; s++)
                    accB[s] = addf2_(accB[s], zredB[(base + s) * 32 + lane]);
            }
            ull aE[4] = {accB[0], accB[2], accB[4], accB[6]};
            ull aO[4] = {accB[1], accB[3], accB[5], accB[7]};
            transpose4_(aE, g);
            transpose4_(aO, g);
            float zg[4][4];
#pragma unroll
            for (int m = 0; m < 4; m++) {
                float2 e = unpack2_(aE[m]), o = unpack2_(aO[m]);
                zg[m][0] = e.x; zg[m][1] = e.y; zg[m][2] = o.x; zg[m][3] = o.y;
            }
            float hv[4];
#pragma unroll
            for (int r = 0; r < 4; r++) {
                float ig = sigmoidf_(zg[0][r] + b1v[0]);
                float fg = sigmoidf_(zg[1][r] + b1v[1]);
                float gg = tanhf(zg[2][r] + b1v[2]);
                float og = sigmoidf_(zg[3][r] + b1v[3]);
                c1[r] = fg * c1[r] + ig * gg;
                hv[r] = og * tanhf(c1[r]);
            }
            *(float4*)&h1w[j * 64 + R] = make_float4(hv[0], hv[1], hv[2], hv[3]);
        }
        grid_sync_(bid, (unsigned)(p + 1));
    }
}

// ---------------------------------------------------------------------------
// k_out: out = tanh( h1_final @ Wo + bo ),  h1 stored transposed hT[k][b]
// ---------------------------------------------------------------------------
__global__ void k_out(const float* __restrict__ Wo, const float* __restrict__ bo,
                      float* __restrict__ out) {
    int idx = blockIdx.x * blockDim.x + threadIdx.x;
    if (idx >= NB * NDOUT) return;
    int n = idx & 127, b = idx >> 7;
    const float* hT = g_h1T;   // h1(512) at parity 0
    float s0 = 0.f, s1 = 0.f, s2 = 0.f, s3 = 0.f;
#pragma unroll 4
    for (int k = 0; k < NH; k += 4) {
        s0 += hT[(k + 0) * 64 + b] * Wo[(size_t)(k + 0) * NDOUT + n];
        s1 += hT[(k + 1) * 64 + b] * Wo[(size_t)(k + 1) * NDOUT + n];
        s2 += hT[(k + 2) * 64 + b] * Wo[(size_t)(k + 2) * NDOUT + n];
        s3 += hT[(k + 3) * 64 + b] * Wo[(size_t)(k + 3) * NDOUT + n];
    }
    out[idx] = tanhf((s0 + s1) + (s2 + s3) + bo[n]);
}

// ---------------------------------------------------------------------------
extern "C" void kernel_launch(void* const* d_in, const int* in_sizes, int n_in,
                              void* d_out, int out_size) {
    const float* x  = (const float*)d_in[0];
    const float* Wi = (const float*)d_in[1];
    const float* bi = (const float*)d_in[2];
    const float* W0 = (const float*)d_in[3];
    const float* U0 = (const float*)d_in[4];
    const float* b0 = (const float*)d_in[5];
    const float* W1 = (const float*)d_in[6];
    const float* U1 = (const float*)d_in[7];
    const float* b1 = (const float*)d_in[8];
    const float* Wo = (const float*)d_in[9];
    const float* bo = (const float*)d_in[10];
    float* out = (float*)d_out;
    (void)in_sizes; (void)n_in; (void)out_size;

    cudaFuncSetAttribute(k_rnn, cudaFuncAttributeMaxDynamicSharedMemorySize, RNN_SMEM);

    k_init<<<512, 256>>>();
    k_prep<<<32768, 256>>>(U0, W1, U1);
    k_xin<<<dim3(16, 512), 256>>>(x, Wi, bi);
    k_p0<<<dim3(32, 256), 256>>>(W0, b0);
    k_rnn<<<NBLK, RNN_THREADS, RNN_SMEM>>>(b1);
    k_out<<<32, 256>>>(Wo, bo, out);
}

// round 15
// speedup vs baseline: 1.1945x; 1.0028x over previous
#include <cuda_runtime.h>
#include <stdint.h>
#include <math.h>

#define NB 64
#define NT 512
#define NF 512
#define NDIN 1024
#define NH 1024
#define NZ 4096
#define NDOUT 128
#define SH (NB*NH)     // 65536 floats per h buffer
#define NBLK 128       // persistent blocks (1/SM, all co-resident)
#define KCH 32         // k per chunk in k_rnn
#define RNN_THREADS 512
// smem: hs 64KB + ws 64KB + zred 48KB
#define RNN_SMEM (65536 + 65536 + 49152)

typedef unsigned long long ull;

// Scratch (device globals; no dynamic allocation allowed)
__device__ float g_xin[(size_t)NT * NB * NDIN];   // tanh(x@Wi+bi), rows r = t*NB+b
__device__ float g_P0[(size_t)NT * NB * NZ];      // xin@W0 + b0
__device__ float g_h0T[2 * SH];                   // transposed h0: [par][j][64 rows]
__device__ float g_h1T[2 * SH];                   // transposed h1
// Region-1 weights (h0-driven), per-lane float2 {U0, W1}:
__device__ float g_WC[(size_t)NBLK * 1024 * 64];    // 32 MB
// Region-2 weights (h1-driven): U1
__device__ float g_WD[(size_t)NBLK * 1024 * 32];    // 16 MB

// grid barrier state: per-block arrival flags + release generation
__device__ volatile unsigned g_flags[NBLK];
__device__ volatile unsigned g_relgen;

// ---------------------------------------------------------------------------
// packed f32x2 helpers (sm_103a dual-fp32 pipe, PTX-only)
// ---------------------------------------------------------------------------
__device__ __forceinline__ ull ffma2_(ull a, ull b, ull c) {
    ull d;
    asm("fma.rn.f32x2 %0, %1, %2, %3;" : "=l"(d) : "l"(a), "l"(b), "l"(c));
    return d;
}
__device__ __forceinline__ ull addf2_(ull a, ull b) {
    ull d;
    asm("add.rn.f32x2 %0, %1, %2;" : "=l"(d) : "l"(a), "l"(b));
    return d;
}
__device__ __forceinline__ float2 unpack2_(ull v) {
    float2 r;
    asm("mov.b64 {%0, %1}, %2;" : "=f"(r.x), "=f"(r.y) : "l"(v));
    return r;
}
__device__ __forceinline__ ull dup2_(float f) {
    ull d;
    asm("mov.b64 %0, {%1, %1};" : "=l"(d) : "f"(f));
    return d;
}

// cp.async, L2-only (.cg) — bypasses L1 so cross-SM h updates are never stale
__device__ __forceinline__ void cp16_(uint32_t dst, const void* src) {
    asm volatile("cp.async.cg.shared.global [%0], [%1], 16;" :: "r"(dst), "l"(src));
}
#define CPCOMMIT() asm volatile("cp.async.commit_group;" ::: "memory")
#define CPWAIT1()  asm volatile("cp.async.wait_group 1;"  ::: "memory")

__device__ __forceinline__ float sigmoidf_(float v) {
    return 1.f / (1.f + __expf(-v));
}

// ---------------------------------------------------------------------------
__global__ void k_init() {
    int idx = blockIdx.x * blockDim.x + threadIdx.x;
    if (idx < 2 * SH) { g_h0T[idx] = 0.f; g_h1T[idx] = 0.f; }
    if (idx < NBLK) g_flags[idx] = 0;
    if (idx == 0) g_relgen = 0;
}

// ---------------------------------------------------------------------------
// k_prep: pack recurrent weights into block-major lane streams.
// ---------------------------------------------------------------------------
__global__ void k_prep(const float* __restrict__ U0, const float* __restrict__ W1,
                       const float* __restrict__ U1) {
    int idx = blockIdx.x * blockDim.x + threadIdx.x;
    const int NWC = NBLK * 1024 * 64;      // 8M
    const int NWD = NBLK * 1024 * 32;      // 4M
    if (idx < NWC) {
        int lane2 = idx & 63, k = (idx >> 6) & 1023, b = idx >> 16;
        int lane = lane2 >> 1, which = lane2 & 1;
        int col = (lane >> 3) * NH + b * 8 + (lane & 7);
        g_WC[idx] = which ? W1[(size_t)k * NZ + col] : U0[(size_t)k * NZ + col];
    }
    if (idx < NWD) {
        int lane = idx & 31, k = (idx >> 5) & 1023, b = idx >> 15;
        int col = (lane >> 3) * NH + b * 8 + (lane & 7);
        g_WD[idx] = U1[(size_t)k * NZ + col];
    }
}

// ---------------------------------------------------------------------------
// k_xin: xin[r, n] = tanh( x[b,t,:] @ Wi[:,n] + bi[n] ),  r = t*NB + b
// ---------------------------------------------------------------------------
__global__ __launch_bounds__(256) void k_xin(const float* __restrict__ x,
                                             const float* __restrict__ Wi,
                                             const float* __restrict__ bi) {
    __shared__ float As[16][64];
    __shared__ float Bs[16][64];
    int tid = threadIdx.x;
    int tx = tid & 15, ty = tid >> 4;
    int n0 = blockIdx.x * 64;
    int row0 = blockIdx.y * 64;

    float acc[4][4] = {};

    int ar = tid & 63, akq = tid >> 6;
    int R = row0 + ar;
    int bb = R & 63, tt = R >> 6;               // r = t*NB + b
    const float* aptr = x + ((size_t)bb * NT + tt) * NF + akq * 4;
    int bkk = tid >> 4, bnq = tid & 15;
    const float* bptr = Wi + (size_t)bkk * NDIN + n0 + bnq * 4;

    float4 pa = *(const float4*)aptr;
    float4 pb = *(const float4*)bptr;

    const int NC = NF / 16;
    for (int c = 0; c < NC; c++) {
        As[akq * 4 + 0][ar] = pa.x; As[akq * 4 + 1][ar] = pa.y;
        As[akq * 4 + 2][ar] = pa.z; As[akq * 4 + 3][ar] = pa.w;
        *(float4*)&Bs[bkk][bnq * 4] = pb;
        __syncthreads();
        if (c + 1 < NC) {
            pa = *(const float4*)(aptr + (c + 1) * 16);
            pb = *(const float4*)(bptr + (size_t)(c + 1) * 16 * NDIN);
        }
#pragma unroll
        for (int kk = 0; kk < 16; kk++) {
            float4 a = *(const float4*)&As[kk][ty * 4];
            float4 b = *(const float4*)&Bs[kk][tx * 4];
            acc[0][0] += a.x * b.x; acc[0][1] += a.x * b.y; acc[0][2] += a.x * b.z; acc[0][3] += a.x * b.w;
            acc[1][0] += a.y * b.x; acc[1][1] += a.y * b.y; acc[1][2] += a.y * b.z; acc[1][3] += a.y * b.w;
            acc[2][0] += a.z * b.x; acc[2][1] += a.z * b.y; acc[2][2] += a.z * b.z; acc[2][3] += a.z * b.w;
            acc[3][0] += a.w * b.x; acc[3][1] += a.w * b.y; acc[3][2] += a.w * b.z; acc[3][3] += a.w * b.w;
        }
        __syncthreads();
    }
#pragma unroll
    for (int i = 0; i < 4; i++) {
        int r = row0 + ty * 4 + i;
#pragma unroll
        for (int jx = 0; jx < 4; jx++) {
            int n = n0 + tx * 4 + jx;
            g_xin[(size_t)r * NDIN + n] = tanhf(acc[i][jx] + bi[n]);
        }
    }
}

// ---------------------------------------------------------------------------
// k_p0 v5: P0 = xin @ W0 + b0. Tile 128x128, 256 threads, 8x8 per thread.
// Per kk: 4x LDS.128 feed 32 FFMA2 — crossbar and fma pipe balanced.
// ---------------------------------------------------------------------------
__global__ __launch_bounds__(256) void k_p0(const float* __restrict__ W0,
                                            const float* __restrict__ b0) {
    __shared__ float As[16][128];
    __shared__ float Bs[16][128];
    int tid = threadIdx.x;
    int tx = tid & 15, ty = tid >> 4;
    int n0 = blockIdx.x * 128;
    int row0 = blockIdx.y * 128;

    ull acc[8][4] = {};              // [row][colpair]

    // A loader: row ar, k-quads akq*4..+3 and akq*4+8..+11
    int ar = tid & 127, akq = tid >> 7;          // akq in {0,1}
    const float* aptr0 = g_xin + (size_t)(row0 + ar) * NDIN + akq * 4;
    const float* aptr1 = aptr0 + 8;
    // B loader: k row bkk, col octet bnq*8 (two float4s)
    int bkk = tid >> 4, bnq = tid & 15;
    const float* bptr0 = W0 + (size_t)bkk * NZ + n0 + bnq * 8;
    const float* bptr1 = bptr0 + 4;

    float4 pa0 = *(const float4*)aptr0;
    float4 pa1 = *(const float4*)aptr1;
    float4 pb0 = *(const float4*)bptr0;
    float4 pb1 = *(const float4*)bptr1;

    const int NC = NDIN / 16;
    for (int c = 0; c < NC; c++) {
        As[akq * 4 + 0][ar] = pa0.x; As[akq * 4 + 1][ar] = pa0.y;
        As[akq * 4 + 2][ar] = pa0.z; As[akq * 4 + 3][ar] = pa0.w;
        As[akq * 4 + 8][ar] = pa1.x; As[akq * 4 + 9][ar] = pa1.y;
        As[akq * 4 + 10][ar] = pa1.z; As[akq * 4 + 11][ar] = pa1.w;
        *(float4*)&Bs[bkk][bnq * 8]     = pb0;
        *(float4*)&Bs[bkk][bnq * 8 + 4] = pb1;
        __syncthreads();
        if (c + 1 < NC) {
            pa0 = *(const float4*)(aptr0 + (c + 1) * 16);
            pa1 = *(const float4*)(aptr1 + (c + 1) * 16);
            pb0 = *(const float4*)(bptr0 + (size_t)(c + 1) * 16 * NZ);
            pb1 = *(const float4*)(bptr1 + (size_t)(c + 1) * 16 * NZ);
        }
#pragma unroll
        for (int kk = 0; kk < 16; kk++) {
            float4 a0 = *(const float4*)&As[kk][ty * 8];
            float4 a1 = *(const float4*)&As[kk][ty * 8 + 4];
            ulonglong2 bA = *(const ulonglong2*)&Bs[kk][tx * 8];      // colpairs 0,1
            ulonglong2 bB = *(const ulonglong2*)&Bs[kk][tx * 8 + 4];  // colpairs 2,3
            ull d;
            d = dup2_(a0.x);
            acc[0][0] = ffma2_(d, bA.x, acc[0][0]); acc[0][1] = ffma2_(d, bA.y, acc[0][1]);
            acc[0][2] = ffma2_(d, bB.x, acc[0][2]); acc[0][3] = ffma2_(d, bB.y, acc[0][3]);
            d = dup2_(a0.y);
            acc[1][0] = ffma2_(d, bA.x, acc[1][0]); acc[1][1] = ffma2_(d, bA.y, acc[1][1]);
            acc[1][2] = ffma2_(d, bB.x, acc[1][2]); acc[1][3] = ffma2_(d, bB.y, acc[1][3]);
            d = dup2_(a0.z);
            acc[2][0] = ffma2_(d, bA.x, acc[2][0]); acc[2][1] = ffma2_(d, bA.y, acc[2][1]);
            acc[2][2] = ffma2_(d, bB.x, acc[2][2]); acc[2][3] = ffma2_(d, bB.y, acc[2][3]);
            d = dup2_(a0.w);
            acc[3][0] = ffma2_(d, bA.x, acc[3][0]); acc[3][1] = ffma2_(d, bA.y, acc[3][1]);
            acc[3][2] = ffma2_(d, bB.x, acc[3][2]); acc[3][3] = ffma2_(d, bB.y, acc[3][3]);
            d = dup2_(a1.x);
            acc[4][0] = ffma2_(d, bA.x, acc[4][0]); acc[4][1] = ffma2_(d, bA.y, acc[4][1]);
            acc[4][2] = ffma2_(d, bB.x, acc[4][2]); acc[4][3] = ffma2_(d, bB.y, acc[4][3]);
            d = dup2_(a1.y);
            acc[5][0] = ffma2_(d, bA.x, acc[5][0]); acc[5][1] = ffma2_(d, bA.y, acc[5][1]);
            acc[5][2] = ffma2_(d, bB.x, acc[5][2]); acc[5][3] = ffma2_(d, bB.y, acc[5][3]);
            d = dup2_(a1.z);
            acc[6][0] = ffma2_(d, bA.x, acc[6][0]); acc[6][1] = ffma2_(d, bA.y, acc[6][1]);
            acc[6][2] = ffma2_(d, bB.x, acc[6][2]); acc[6][3] = ffma2_(d, bB.y, acc[6][3]);
            d = dup2_(a1.w);
            acc[7][0] = ffma2_(d, bA.x, acc[7][0]); acc[7][1] = ffma2_(d, bA.y, acc[7][1]);
            acc[7][2] = ffma2_(d, bB.x, acc[7][2]); acc[7][3] = ffma2_(d, bB.y, acc[7][3]);
        }
        __syncthreads();
    }
    int n = n0 + tx * 8;
    float4 bv0 = *(const float4*)&b0[n];
    float4 bv1 = *(const float4*)&b0[n + 4];
#pragma unroll
    for (int i = 0; i < 8; i++) {
        int r = row0 + ty * 8 + i;
        float2 v0 = unpack2_(acc[i][0]);
        float2 v1 = unpack2_(acc[i][1]);
        float2 v2 = unpack2_(acc[i][2]);
        float2 v3 = unpack2_(acc[i][3]);
        float4 o0 = make_float4(v0.x + bv0.x, v0.y + bv0.y, v1.x + bv0.z, v1.y + bv0.w);
        float4 o1 = make_float4(v2.x + bv1.x, v2.y + bv1.y, v3.x + bv1.z, v3.y + bv1.w);
        *(float4*)&g_P0[(size_t)r * NZ + n]     = o0;
        *(float4*)&g_P0[(size_t)r * NZ + n + 4] = o1;
    }
}

// ---------------------------------------------------------------------------
// flag-array grid barrier (round-12 version)
// ---------------------------------------------------------------------------
__device__ __forceinline__ void grid_sync_(int bid, unsigned ph) {
    __syncthreads();
    if (threadIdx.x == 0) {
        __threadfence();
        g_flags[bid] = ph;
    }
    if (bid == 0) {
        if (threadIdx.x < NBLK) {
            while (g_flags[threadIdx.x] < ph) { }
        }
        __syncthreads();
        if (threadIdx.x == 0) g_relgen = ph;
    }
    if (threadIdx.x == 0) {
        while (g_relgen < ph) { }
        __threadfence();
    }
    __syncthreads();
}

// ---------------------------------------------------------------------------
// 4x4 transpose among lanes {u, u+8, u+16, u+24} (bits 3,4 of lane).
// ---------------------------------------------------------------------------
__device__ __forceinline__ void transpose4_(ull acc[4], int g) {
    ull x0 = (g & 1) ? acc[0] : acc[1];
    ull x1 = (g & 1) ? acc[2] : acc[3];
    x0 = __shfl_xor_sync(0xffffffffu, x0, 8);
    x1 = __shfl_xor_sync(0xffffffffu, x1, 8);
    if (g & 1) { acc[0] = x0; acc[2] = x1; } else { acc[1] = x0; acc[3] = x1; }
    x0 = (g & 2) ? acc[0] : acc[2];
    x1 = (g & 2) ? acc[1] : acc[3];
    x0 = __shfl_xor_sync(0xffffffffu, x0, 16);
    x1 = __shfl_xor_sync(0xffffffffu, x1, 16);
    if (g & 2) { acc[0] = x0; acc[1] = x1; } else { acc[2] = x0; acc[3] = x1; }
}

// ---------------------------------------------------------------------------
// k_rnn v5 (round-12 version): merged-phase recurrence + dual epilogue.
// Phase p: z0(p) (h0(p+1), p<512) and z1(p-1) (h1(p), p>0) in one 3072-K
// pass, one grid sync. 4-way split-K, named barrier per grp.
// Tail: grp 0 reduces+finishes layer 0, grp 1 layer 1, concurrently.
// ---------------------------------------------------------------------------
__global__ __launch_bounds__(RNN_THREADS, 1) void k_rnn(const float* __restrict__ b1) {
    extern __shared__ __align__(16) unsigned char sraw[];
    // hs [4][2][32][64] 64KB | ws [4][2][2048f] 64KB | zredA 24KB | zredB 24KB
    ull* zredA = (ull*)(sraw + 131072);
    ull* zredB = zredA + 3072;

    int tid = threadIdx.x;
    int grp = tid >> 7, gtid = tid & 127;
    int wg = (gtid >> 5), lane = tid & 31;
    int u = lane & 7, g = lane >> 3;
    int bid = blockIdx.x, j = bid * 8 + u;
    int R = wg * 16 + g * 4;                     // epilogue base row

    uint32_t sbase = (uint32_t)__cvta_generic_to_shared(sraw);
    uint32_t hdst = sbase + grp * 16384;
    uint32_t wdst = sbase + 65536 + grp * 16384;
    const float* hs_rd = (const float*)sraw + grp * 4096;
    const float* ws_rd = (const float*)(sraw + 65536) + grp * 4096;

    const float* wcg = g_WC + (size_t)bid * 1024 * 64 + (size_t)grp * 256 * 64;
    const float* wdg = g_WD + (size_t)bid * 1024 * 32 + (size_t)grp * 256 * 32;

    float b1v[4];
#pragma unroll
    for (int m = 0; m < 4; m++) b1v[m] = b1[m * NH + j];
    float c0[4] = {0.f, 0.f, 0.f, 0.f};
    float c1[4] = {0.f, 0.f, 0.f, 0.f};

    for (int p = 0; p <= NT; p++) {
        int par = p & 1;
        const float* h0g = g_h0T + (size_t)par * SH + (size_t)grp * 256 * 64;
        const float* h1g = g_h1T + (size_t)(par ^ 1) * SH + (size_t)grp * 256 * 64;
        float* h0w = g_h0T + (size_t)(par ^ 1) * SH;   // h0(p+1)
        float* h1w = g_h1T + (size_t)par * SH;         // h1(p)

        // P0 prefetch for layer-0 epilogue (grp 0 only, p<512)
        float pz[4][4];
        if (grp == 0 && p < NT) {
            size_t pb = ((size_t)p * NB + R) * NZ + j;
#pragma unroll
            for (int r = 0; r < 4; r++)
#pragma unroll
                for (int m = 0; m < 4; m++)
                    pz[r][m] = g_P0[pb + (size_t)r * NZ + m * NH];
        }

        ull accA[8] = {0ull,0ull,0ull,0ull,0ull,0ull,0ull,0ull};
        ull accB[8] = {0ull,0ull,0ull,0ull,0ull,0ull,0ull,0ull};

        auto barg = [&] {
            asm volatile("bar.sync %0, %1;" :: "r"(grp + 1), "r"(128) : "memory");
        };
        auto load = [&](int buf, int c) {
            const char* hp;
            const char* wp;
            int nw;
            if (c < 8) {
                hp = (const char*)(h0g + c * 2048);
                wp = (const char*)(wcg + (size_t)c * 2048);
                nw = 4;
            } else {
                hp = (const char*)(h1g + (c - 8) * 2048);
                wp = (const char*)(wdg + (size_t)(c - 8) * 1024);
                nw = 2;
            }
            hp += gtid * 16;
            uint32_t hd = hdst + buf * 8192 + gtid * 16;
            cp16_(hd, hp); cp16_(hd + 2048, hp + 2048);
            cp16_(hd + 4096, hp + 4096); cp16_(hd + 6144, hp + 6144);
            wp += gtid * 16;
            uint32_t wd = wdst + buf * 8192 + gtid * 16;
            cp16_(wd, wp); cp16_(wd + 2048, wp + 2048);
            if (nw == 4) { cp16_(wd + 4096, wp + 4096); cp16_(wd + 6144, wp + 6144); }
        };

        load(0, 0); CPCOMMIT();
        load(1, 1); CPCOMMIT();
        CPWAIT1(); barg();

        for (int c = 0; c < 16; c++) {
            int buf = c & 1;
            const float* hC = hs_rd + buf * 2048 + wg * 16;
            if (c < 8) {
                const float2* wC = (const float2*)(ws_rd + buf * 2048);
#pragma unroll 8
                for (int kk = 0; kk < KCH; kk++) {
                    ulonglong2 hA = *(const ulonglong2*)(hC + kk * 64);
                    ulonglong2 hB = *(const ulonglong2*)(hC + kk * 64 + 4);
                    ulonglong2 hCc = *(const ulonglong2*)(hC + kk * 64 + 8);
                    ulonglong2 hD = *(const ulonglong2*)(hC + kk * 64 + 12);
                    float2 wv = wC[kk * 32 + lane];
                    ull d0 = dup2_(wv.x);
                    ull d1 = dup2_(wv.y);
                    accA[0] = ffma2_(hA.x, d0, accA[0]);
                    accA[1] = ffma2_(hA.y, d0, accA[1]);
                    accA[2] = ffma2_(hB.x, d0, accA[2]);
                    accA[3] = ffma2_(hB.y, d0, accA[3]);
                    accA[4] = ffma2_(hCc.x, d0, accA[4]);
                    accA[5] = ffma2_(hCc.y, d0, accA[5]);
                    accA[6] = ffma2_(hD.x, d0, accA[6]);
                    accA[7] = ffma2_(hD.y, d0, accA[7]);
                    accB[0] = ffma2_(hA.x, d1, accB[0]);
                    accB[1] = ffma2_(hA.y, d1, accB[1]);
                    accB[2] = ffma2_(hB.x, d1, accB[2]);
                    accB[3] = ffma2_(hB.y, d1, accB[3]);
                    accB[4] = ffma2_(hCc.x, d1, accB[4]);
                    accB[5] = ffma2_(hCc.y, d1, accB[5]);
                    accB[6] = ffma2_(hD.x, d1, accB[6]);
                    accB[7] = ffma2_(hD.y, d1, accB[7]);
                }
            } else {
                const float* wC = ws_rd + buf * 2048;
#pragma unroll 8
                for (int kk = 0; kk < KCH; kk++) {
                    ulonglong2 hA = *(const ulonglong2*)(hC + kk * 64);
                    ulonglong2 hB = *(const ulonglong2*)(hC + kk * 64 + 4);
                    ulonglong2 hCc = *(const ulonglong2*)(hC + kk * 64 + 8);
                    ulonglong2 hD = *(const ulonglong2*)(hC + kk * 64 + 12);
                    ull d1 = dup2_(wC[kk * 32 + lane]);
                    accB[0] = ffma2_(hA.x, d1, accB[0]);
                    accB[1] = ffma2_(hA.y, d1, accB[1]);
                    accB[2] = ffma2_(hB.x, d1, accB[2]);
                    accB[3] = ffma2_(hB.y, d1, accB[3]);
                    accB[4] = ffma2_(hCc.x, d1, accB[4]);
                    accB[5] = ffma2_(hCc.y, d1, accB[5]);
                    accB[6] = ffma2_(hD.x, d1, accB[6]);
                    accB[7] = ffma2_(hD.y, d1, accB[7]);
                }
            }
            barg();
            if (c + 2 < 16) load(buf, c + 2);
            CPCOMMIT(); CPWAIT1(); barg();
        }

        // ---- write partials (A: grps 1-3; B: grps 0,2,3) ----
        if (grp != 0) {
            int base = ((grp - 1) * 4 + wg) * 8;
#pragma unroll
            for (int s = 0; s < 8; s++) zredA[(base + s) * 32 + lane] = accA[s];
        }
        if (grp != 1) {
            int qb = (grp == 0) ? 0 : grp - 1;
            int base = (qb * 4 + wg) * 8;
#pragma unroll
            for (int s = 0; s < 8; s++) zredB[(base + s) * 32 + lane] = accB[s];
        }
        __syncthreads();

        if (grp == 0 && p < NT) {
            // ---- layer-0 epilogue: h0(p+1) ----
#pragma unroll
            for (int q = 0; q < 3; q++) {
                int base = (q * 4 + wg) * 8;
#pragma unroll
                for (int s = 0; s < 8; s++)
                    accA[s] = addf2_(accA[s], zredA[(base + s) * 32 + lane]);
            }
            ull aE[4] = {accA[0], accA[2], accA[4], accA[6]};
            ull aO[4] = {accA[1], accA[3], accA[5], accA[7]};
            transpose4_(aE, g);
            transpose4_(aO, g);
            float zg[4][4];
#pragma unroll
            for (int m = 0; m < 4; m++) {
                float2 e = unpack2_(aE[m]), o = unpack2_(aO[m]);
                zg[m][0] = e.x; zg[m][1] = e.y; zg[m][2] = o.x; zg[m][3] = o.y;
            }
            float hv[4];
#pragma unroll
            for (int r = 0; r < 4; r++) {
                float ig = sigmoidf_(zg[0][r] + pz[r][0]);
                float fg = sigmoidf_(zg[1][r] + pz[r][1]);
                float gg = tanhf(zg[2][r] + pz[r][2]);
                float og = sigmoidf_(zg[3][r] + pz[r][3]);
                c0[r] = fg * c0[r] + ig * gg;
                hv[r] = og * tanhf(c0[r]);
            }
            *(float4*)&h0w[j * 64 + R] = make_float4(hv[0], hv[1], hv[2], hv[3]);
        } else if (grp == 1 && p > 0) {
            // ---- layer-1 epilogue: h1(p) ----
#pragma unroll
            for (int q = 0; q < 3; q++) {
                int base = (q * 4 + wg) * 8;
#pragma unroll
                for (int s = 0; s < 8; s++)
                    accB[s] = addf2_(accB[s], zredB[(base + s) * 32 + lane]);
            }
            ull aE[4] = {accB[0], accB[2], accB[4], accB[6]};
            ull aO[4] = {accB[1], accB[3], accB[5], accB[7]};
            transpose4_(aE, g);
            transpose4_(aO, g);
            float zg[4][4];
#pragma unroll
            for (int m = 0; m < 4; m++) {
                float2 e = unpack2_(aE[m]), o = unpack2_(aO[m]);
                zg[m][0] = e.x; zg[m][1] = e.y; zg[m][2] = o.x; zg[m][3] = o.y;
            }
            float hv[4];
#pragma unroll
            for (int r = 0; r < 4; r++) {
                float ig = sigmoidf_(zg[0][r] + b1v[0]);
                float fg = sigmoidf_(zg[1][r] + b1v[1]);
                float gg = tanhf(zg[2][r] + b1v[2]);
                float og = sigmoidf_(zg[3][r] + b1v[3]);
                c1[r] = fg * c1[r] + ig * gg;
                hv[r] = og * tanhf(c1[r]);
            }
            *(float4*)&h1w[j * 64 + R] = make_float4(hv[0], hv[1], hv[2], hv[3]);
        }
        grid_sync_(bid, (unsigned)(p + 1));
    }
}

// ---------------------------------------------------------------------------
// k_out: out = tanh( h1_final @ Wo + bo ),  h1 stored transposed hT[k][b]
// ---------------------------------------------------------------------------
__global__ void k_out(const float* __restrict__ Wo, const float* __restrict__ bo,
                      float* __restrict__ out) {
    int idx = blockIdx.x * blockDim.x + threadIdx.x;
    if (idx >= NB * NDOUT) return;
    int n = idx & 127, b = idx >> 7;
    const float* hT = g_h1T;   // h1(512) at parity 0
    float s0 = 0.f, s1 = 0.f, s2 = 0.f, s3 = 0.f;
#pragma unroll 4
    for (int k = 0; k < NH; k += 4) {
        s0 += hT[(k + 0) * 64 + b] * Wo[(size_t)(k + 0) * NDOUT + n];
        s1 += hT[(k + 1) * 64 + b] * Wo[(size_t)(k + 1) * NDOUT + n];
        s2 += hT[(k + 2) * 64 + b] * Wo[(size_t)(k + 2) * NDOUT + n];
        s3 += hT[(k + 3) * 64 + b] * Wo[(size_t)(k + 3) * NDOUT + n];
    }
    out[idx] = tanhf((s0 + s1) + (s2 + s3) + bo[n]);
}

// ---------------------------------------------------------------------------
extern "C" void kernel_launch(void* const* d_in, const int* in_sizes, int n_in,
                              void* d_out, int out_size) {
    const float* x  = (const float*)d_in[0];
    const float* Wi = (const float*)d_in[1];
    const float* bi = (const float*)d_in[2];
    const float* W0 = (const float*)d_in[3];
    const float* U0 = (const float*)d_in[4];
    const float* b0 = (const float*)d_in[5];
    const float* W1 = (const float*)d_in[6];
    const float* U1 = (const float*)d_in[7];
    const float* b1 = (const float*)d_in[8];
    const float* Wo = (const float*)d_in[9];
    const float* bo = (const float*)d_in[10];
    float* out = (float*)d_out;
    (void)in_sizes; (void)n_in; (void)out_size;

    cudaFuncSetAttribute(k_rnn, cudaFuncAttributeMaxDynamicSharedMemorySize, RNN_SMEM);

    k_init<<<512, 256>>>();
    k_prep<<<32768, 256>>>(U0, W1, U1);
    k_xin<<<dim3(16, 512), 256>>>(x, Wi, bi);
    k_p0<<<dim3(32, 256), 256>>>(W0, b0);
    k_rnn<<<NBLK, RNN_THREADS, RNN_SMEM>>>(b1);
    k_out<<<32, 256>>>(Wo, bo, out);
}